// round 10
// baseline (speedup 1.0000x reference)
#include <cuda_runtime.h>

// NNLoss: out = sum_{b,h,w} min_{di,dj in [-2,2]} sum_c |gt[b,c,h+di,w+dj] - pred[b,c,h,w]|
// with out-of-image gt treated as +1e30 (never wins the min).
//
// Shapes fixed by the problem: B=16, C=3, H=W=256, fp32.

#define BB   16
#define CC   3
#define HH   256
#define WW   256
#define TILE_W 128       // pixels in w per block (32 threads x 4 px each)
#define TILE_H 8         // pixels in h per block
#define SROWS (TILE_H + 4)   // 12
#define SCOLS (TILE_W + 4)   // 132 (multiple of 4 -> LDS.128 alignment holds)
#define BIGV 1e30f
#define NBLK (2 * 32 * 16)   // 1024 blocks total

__device__ float g_partial[NBLK];

__global__ __launch_bounds__(256, 4)
void nnloss_main(const float* __restrict__ pred, const float* __restrict__ gt) {
    __shared__ __align__(16) float sg[CC * SROWS * SCOLS];
    __shared__ float sred[256];

    const int tx  = threadIdx.x;          // 0..31
    const int ty  = threadIdx.y;          // 0..7
    const int tid = ty * 32 + tx;
    const int b   = blockIdx.z;
    const int h0  = blockIdx.y * TILE_H;
    const int w0  = blockIdx.x * TILE_W;

    const float* gtb = gt + (size_t)b * CC * HH * WW;

    // ---- Cooperative fill of the 3-channel halo tile (halo value = BIGV) ----
    const int TOT = CC * SROWS * SCOLS;   // 4752
    for (int i = tid; i < TOT; i += 256) {
        int c   = i / (SROWS * SCOLS);
        int rem = i - c * (SROWS * SCOLS);
        int r   = rem / SCOLS;
        int s   = rem - r * SCOLS;
        int gr  = h0 + r - 2;
        int gc  = w0 + s - 2;
        float v = BIGV;
        if ((unsigned)gr < HH && (unsigned)gc < WW)
            v = __ldg(&gtb[c * HH * WW + gr * WW + gc]);
        sg[i] = v;
    }
    __syncthreads();

    // ---- Each thread: 4 contiguous output pixels (h0+ty, w0 + tx*4 + 0..3) ----
    const int h     = h0 + ty;
    const int wbase = w0 + tx * 4;
    const float* pb = pred + (size_t)b * CC * HH * WW + h * WW + wbase;

    float4 q0 = *(const float4*)(pb + 0 * HH * WW);
    float4 q1 = *(const float4*)(pb + 1 * HH * WW);
    float4 q2 = *(const float4*)(pb + 2 * HH * WW);
    float p0[4] = {q0.x, q0.y, q0.z, q0.w};
    float p1[4] = {q1.x, q1.y, q1.z, q1.w};
    float p2[4] = {q2.x, q2.y, q2.z, q2.w};

    float m[4] = {BIGV, BIGV, BIGV, BIGV};

    #pragma unroll
    for (int di = 0; di < 5; di++) {
        // 8-float windows per channel (two aligned LDS.128 each):
        // sg[c][ty+di][tx*4 .. tx*4+7] -> gt cols wbase-2 .. wbase+5
        const int rowoff = (ty + di) * SCOLS + tx * 4;
        float4 a0 = *(const float4*)&sg[0 * SROWS * SCOLS + rowoff];
        float4 b0 = *(const float4*)&sg[0 * SROWS * SCOLS + rowoff + 4];
        float4 a1 = *(const float4*)&sg[1 * SROWS * SCOLS + rowoff];
        float4 b1 = *(const float4*)&sg[1 * SROWS * SCOLS + rowoff + 4];
        float4 a2 = *(const float4*)&sg[2 * SROWS * SCOLS + rowoff];
        float4 b2 = *(const float4*)&sg[2 * SROWS * SCOLS + rowoff + 4];
        float w0a[8] = {a0.x, a0.y, a0.z, a0.w, b0.x, b0.y, b0.z, b0.w};
        float w1a[8] = {a1.x, a1.y, a1.z, a1.w, b1.x, b1.y, b1.z, b1.w};
        float w2a[8] = {a2.x, a2.y, a2.z, a2.w, b2.x, b2.y, b2.z, b2.w};

        #pragma unroll
        for (int dj = 0; dj < 5; dj++) {
            #pragma unroll
            for (int k = 0; k < 4; k++) {
                float s = fabsf(w0a[k + dj] - p0[k])
                        + fabsf(w1a[k + dj] - p1[k])
                        + fabsf(w2a[k + dj] - p2[k]);
                m[k] = fminf(m[k], s);
            }
        }
    }

    // ---- Deterministic block reduction of the 4 per-thread mins ----
    float local = (m[0] + m[1]) + (m[2] + m[3]);
    sred[tid] = local;
    __syncthreads();
    #pragma unroll
    for (int off = 128; off > 0; off >>= 1) {
        if (tid < off) sred[tid] += sred[tid + off];
        __syncthreads();
    }
    if (tid == 0) {
        int blin = blockIdx.x + gridDim.x * (blockIdx.y + gridDim.y * blockIdx.z);
        g_partial[blin] = sred[0];
    }
}

__global__ __launch_bounds__(256)
void nnloss_reduce(float* __restrict__ out) {
    __shared__ float s[256];
    int t = threadIdx.x;
    s[t] = (g_partial[t] + g_partial[t + 256])
         + (g_partial[t + 512] + g_partial[t + 768]);
    __syncthreads();
    #pragma unroll
    for (int off = 128; off > 0; off >>= 1) {
        if (t < off) s[t] += s[t + off];
        __syncthreads();
    }
    if (t == 0) out[0] = s[0];
}

extern "C" void kernel_launch(void* const* d_in, const int* in_sizes, int n_in,
                              void* d_out, int out_size) {
    const float* pred = (const float*)d_in[0];
    const float* gt   = (const float*)d_in[1];
    float* out        = (float*)d_out;
    (void)in_sizes; (void)n_in; (void)out_size;

    dim3 block(32, 8, 1);
    dim3 grid(WW / TILE_W, HH / TILE_H, BB);   // (2, 32, 16) = 1024 blocks
    nnloss_main<<<grid, block>>>(pred, gt);
    nnloss_reduce<<<1, 256>>>(out);
}

// round 11
// speedup vs baseline: 1.0197x; 1.0197x over previous
#include <cuda_runtime.h>

// NNLoss: out = sum_{b,h,w} min_{di,dj in [-2,2]} sum_c |gt[b,c,h+di,w+dj] - pred[b,c,h,w]|
// with out-of-image gt treated as +1e30 (never wins the min).
//
// Shapes fixed by the problem: B=16, C=3, H=W=256, fp32.

#define BB   16
#define CC   3
#define HH   256
#define WW   256
#define TILE_W 128       // pixels in w per block (32 threads x 4 px each)
#define TILE_H 8         // pixels in h per block
#define SROWS (TILE_H + 4)   // 12
#define SCOLS (TILE_W + 4)   // 132 (multiple of 4 -> LDS.128 alignment holds)
#define BIGV 1e30f
#define NBLK (2 * 32 * 16)   // 1024 blocks total

__device__ float g_partial[NBLK];

__global__ __launch_bounds__(256, 4)
void nnloss_main(const float* __restrict__ pred, const float* __restrict__ gt) {
    __shared__ __align__(16) float sg[CC * SROWS * SCOLS];
    __shared__ float sred[256];

    const int tx  = threadIdx.x;          // 0..31
    const int ty  = threadIdx.y;          // 0..7
    const int tid = ty * 32 + tx;
    const int b   = blockIdx.z;
    const int h0  = blockIdx.y * TILE_H;
    const int w0  = blockIdx.x * TILE_W;

    const float* gtb = gt + (size_t)b * CC * HH * WW;

    // ---- Cooperative fill of the 3-channel halo tile (halo value = BIGV) ----
    const int TOT = CC * SROWS * SCOLS;   // 4752
    for (int i = tid; i < TOT; i += 256) {
        int c   = i / (SROWS * SCOLS);
        int rem = i - c * (SROWS * SCOLS);
        int r   = rem / SCOLS;
        int s   = rem - r * SCOLS;
        int gr  = h0 + r - 2;
        int gc  = w0 + s - 2;
        float v = BIGV;
        if ((unsigned)gr < HH && (unsigned)gc < WW)
            v = __ldg(&gtb[c * HH * WW + gr * WW + gc]);
        sg[i] = v;
    }
    __syncthreads();

    // ---- Each thread: 4 contiguous output pixels (h0+ty, w0 + tx*4 + 0..3) ----
    const int h     = h0 + ty;
    const int wbase = w0 + tx * 4;
    const float* pb = pred + (size_t)b * CC * HH * WW + h * WW + wbase;

    float4 q0 = *(const float4*)(pb + 0 * HH * WW);
    float4 q1 = *(const float4*)(pb + 1 * HH * WW);
    float4 q2 = *(const float4*)(pb + 2 * HH * WW);
    float p0[4] = {q0.x, q0.y, q0.z, q0.w};
    float p1[4] = {q1.x, q1.y, q1.z, q1.w};
    float p2[4] = {q2.x, q2.y, q2.z, q2.w};

    float m[4] = {BIGV, BIGV, BIGV, BIGV};

    #pragma unroll
    for (int di = 0; di < 5; di++) {
        // 8-float windows per channel (two aligned LDS.128 each):
        // sg[c][ty+di][tx*4 .. tx*4+7] -> gt cols wbase-2 .. wbase+5
        const int rowoff = (ty + di) * SCOLS + tx * 4;
        float4 a0 = *(const float4*)&sg[0 * SROWS * SCOLS + rowoff];
        float4 b0 = *(const float4*)&sg[0 * SROWS * SCOLS + rowoff + 4];
        float4 a1 = *(const float4*)&sg[1 * SROWS * SCOLS + rowoff];
        float4 b1 = *(const float4*)&sg[1 * SROWS * SCOLS + rowoff + 4];
        float4 a2 = *(const float4*)&sg[2 * SROWS * SCOLS + rowoff];
        float4 b2 = *(const float4*)&sg[2 * SROWS * SCOLS + rowoff + 4];
        float w0a[8] = {a0.x, a0.y, a0.z, a0.w, b0.x, b0.y, b0.z, b0.w};
        float w1a[8] = {a1.x, a1.y, a1.z, a1.w, b1.x, b1.y, b1.z, b1.w};
        float w2a[8] = {a2.x, a2.y, a2.z, a2.w, b2.x, b2.y, b2.z, b2.w};

        #pragma unroll
        for (int dj = 0; dj < 5; dj++) {
            #pragma unroll
            for (int k = 0; k < 4; k++) {
                float s = fabsf(w0a[k + dj] - p0[k])
                        + fabsf(w1a[k + dj] - p1[k])
                        + fabsf(w2a[k + dj] - p2[k]);
                m[k] = fminf(m[k], s);
            }
        }
    }

    // ---- Deterministic block reduction of the 4 per-thread mins ----
    float local = (m[0] + m[1]) + (m[2] + m[3]);
    sred[tid] = local;
    __syncthreads();
    #pragma unroll
    for (int off = 128; off > 0; off >>= 1) {
        if (tid < off) sred[tid] += sred[tid + off];
        __syncthreads();
    }
    if (tid == 0) {
        int blin = blockIdx.x + gridDim.x * (blockIdx.y + gridDim.y * blockIdx.z);
        g_partial[blin] = sred[0];
    }
}

__global__ __launch_bounds__(256)
void nnloss_reduce(float* __restrict__ out) {
    __shared__ float s[256];
    int t = threadIdx.x;
    s[t] = (g_partial[t] + g_partial[t + 256])
         + (g_partial[t + 512] + g_partial[t + 768]);
    __syncthreads();
    #pragma unroll
    for (int off = 128; off > 0; off >>= 1) {
        if (t < off) s[t] += s[t + off];
        __syncthreads();
    }
    if (t == 0) out[0] = s[0];
}

extern "C" void kernel_launch(void* const* d_in, const int* in_sizes, int n_in,
                              void* d_out, int out_size) {
    const float* pred = (const float*)d_in[0];
    const float* gt   = (const float*)d_in[1];
    float* out        = (float*)d_out;
    (void)in_sizes; (void)n_in; (void)out_size;

    dim3 block(32, 8, 1);
    dim3 grid(WW / TILE_W, HH / TILE_H, BB);   // (2, 32, 16) = 1024 blocks
    nnloss_main<<<grid, block>>>(pred, gt);
    nnloss_reduce<<<1, 256>>>(out);
}